// round 12
// baseline (speedup 1.0000x reference)
#include <cuda_runtime.h>
#include <cuda_fp16.h>
#include <cstdint>

#define NN 50000
#define NE 800000
#define NB 98        // scan blocks: 98*512 >= 50000
#define HA 25088     // first-half nodes (multiple of 128, 64, 16)
#define HB (NN - HA) // 24912 (multiple of 8)

// ---------------------------------------------------------------------------
// Scratch (static device arrays: allocation-free per harness rules)
// ---------------------------------------------------------------------------
__device__ __half g_tmpA[NN * 128];
__device__ __half g_tmpB[NN * 128];
__device__ float  g_h[NN * 128];
__device__ float  g_dinv[NN];
__device__ int    g_deg[NN];
__device__ int    g_rowptr[NN + 1];
__device__ int    g_cursor[NN];
__device__ int    g_csr[NE];
__device__ int    g_bsum[NB];

// ---------------------------------------------------------------------------
// Host-side stream/event context (host resources only; created at static init)
// ---------------------------------------------------------------------------
struct Ctx {
    cudaStream_t s;
    cudaEvent_t e[12];
    Ctx() {
        cudaStreamCreateWithFlags(&s, cudaStreamNonBlocking);
        for (int i = 0; i < 12; i++) cudaEventCreateWithFlags(&e[i], cudaEventDisableTiming);
    }
};
static Ctx g_ctx;

// ---------------------------------------------------------------------------
// degree / normalization
// ---------------------------------------------------------------------------
__global__ void k_deg_init(int* __restrict__ deg) {
    int i = blockIdx.x * blockDim.x + threadIdx.x;
    if (i < NN) deg[i] = 1;  // self-loop
}
__global__ void k_deg_count(const int* __restrict__ ei, int* __restrict__ deg) {
    int e = blockIdx.x * blockDim.x + threadIdx.x;
    if (e < NE) atomicAdd(&deg[ei[NE + e]], 1);
}

// ---------------------------------------------------------------------------
// CSR build: scan1 (block-local exclusive scan + dinv), scan3 (+cross-block
// base reduction), cursor fill.
// ---------------------------------------------------------------------------
__global__ void k_scan1(const int* __restrict__ deg, int* __restrict__ rowptr,
                        int* __restrict__ bsum, float* __restrict__ dinv) {
    __shared__ int s[512];
    int tid = threadIdx.x;
    int i = blockIdx.x * 512 + tid;
    int d = (i < NN) ? deg[i] : 1;
    if (i < NN) dinv[i] = rsqrtf((float)d);
    int v = (i < NN) ? (d - 1) : 0;
    s[tid] = v;
    __syncthreads();
    for (int o = 1; o < 512; o <<= 1) {
        int t = (tid >= o) ? s[tid - o] : 0;
        __syncthreads();
        s[tid] += t;
        __syncthreads();
    }
    if (i < NN) rowptr[i] = s[tid] - v;
    if (tid == 511) bsum[blockIdx.x] = s[511];
}
__global__ void k_scan3(int* __restrict__ rowptr, const int* __restrict__ bsum,
                        int* __restrict__ cursor) {
    __shared__ int sb[128];
    int tid = threadIdx.x;
    if (tid < 128) sb[tid] = (tid < blockIdx.x && tid < NB) ? bsum[tid] : 0;
    __syncthreads();
    for (int o = 64; o > 0; o >>= 1) {
        if (tid < o) sb[tid] += sb[tid + o];
        __syncthreads();
    }
    int base = sb[0];
    int i = blockIdx.x * 512 + tid;
    if (i < NN) {
        int r = rowptr[i] + base;
        rowptr[i] = r;
        cursor[i] = r;
    }
    if (blockIdx.x == 0 && tid == 0) rowptr[NN] = NE;
}
__global__ void k_fill(const int* __restrict__ ei, int* __restrict__ cursor,
                       int* __restrict__ csr) {
    int e = blockIdx.x * blockDim.x + threadIdx.x;
    if (e >= NE) return;
    int dst = ei[NE + e];
    int pos = atomicAdd(&cursor[dst], 1);
    csr[pos] = ei[e];
}

// ---------------------------------------------------------------------------
// Tensor-core GEMM (HMMA mma.sync): 128x128 tile per block, 8 warps.
// out[row] = fp16( (A[row] @ W) [* scale[row]] ); fp32 accumulate.
// ---------------------------------------------------------------------------
static constexpr int MMA_SMEM_BYTES = 2 * 128 * 136 * 2;   // 69632

__global__ void __launch_bounds__(256)
k_gemm_mma(const float* __restrict__ A, const float* __restrict__ W,
           const float* __restrict__ scale, __half* __restrict__ out, int nrows) {
    extern __shared__ __half sh[];
    __half* As = sh;               // [128][136]
    __half* Bs = sh + 128 * 136;   // [128][136]  (W[k][n])
    const int tid = threadIdx.x;
    const int wid = tid >> 5, lane = tid & 31;
    const int row0 = blockIdx.x * 128;

    for (int i = tid; i < 4096; i += 256) {
        int k = i >> 5, nq = i & 31;
        float4 f = ((const float4*)W)[i];
        __half* p = Bs + k * 136 + nq * 4;
        *(__half2*)p       = __floats2half2_rn(f.x, f.y);
        *(__half2*)(p + 2) = __floats2half2_rn(f.z, f.w);
    }
    for (int i = tid; i < 4096; i += 256) {
        int r = i >> 5, kq = i & 31;
        int grow = row0 + r;
        float4 f = make_float4(0.f, 0.f, 0.f, 0.f);
        if (grow < nrows) f = ((const float4*)A)[(size_t)grow * 32 + kq];
        __half* p = As + r * 136 + kq * 4;
        *(__half2*)p       = __floats2half2_rn(f.x, f.y);
        *(__half2*)(p + 2) = __floats2half2_rn(f.z, f.w);
    }
    __syncthreads();

    float cf[16][4];
#pragma unroll
    for (int t = 0; t < 16; t++) { cf[t][0] = cf[t][1] = cf[t][2] = cf[t][3] = 0.f; }

    const int wr0 = wid * 16;
    uint32_t a_base = (uint32_t)__cvta_generic_to_shared(
        As + (wr0 + (lane & 15)) * 136 + (lane >> 4) * 8);
    uint32_t b_base = (uint32_t)__cvta_generic_to_shared(
        Bs + (lane & 15) * 136 + (lane >> 4) * 8);

#pragma unroll
    for (int ks = 0; ks < 8; ks++) {
        uint32_t a0, a1, a2, a3;
        asm volatile("ldmatrix.sync.aligned.m8n8.x4.shared.b16 {%0,%1,%2,%3}, [%4];"
                     : "=r"(a0), "=r"(a1), "=r"(a2), "=r"(a3)
                     : "r"(a_base + ks * 16 * 2));
#pragma unroll
        for (int nt = 0; nt < 8; nt++) {
            uint32_t b0, b1, b2, b3;
            asm volatile("ldmatrix.sync.aligned.m8n8.x4.trans.shared.b16 {%0,%1,%2,%3}, [%4];"
                         : "=r"(b0), "=r"(b1), "=r"(b2), "=r"(b3)
                         : "r"(b_base + (ks * 16 * 136 + nt * 16) * 2));
            asm volatile(
                "mma.sync.aligned.m16n8k16.row.col.f32.f16.f16.f32 "
                "{%0,%1,%2,%3}, {%4,%5,%6,%7}, {%8,%9}, {%0,%1,%2,%3};"
                : "+f"(cf[2 * nt][0]), "+f"(cf[2 * nt][1]),
                  "+f"(cf[2 * nt][2]), "+f"(cf[2 * nt][3])
                : "r"(a0), "r"(a1), "r"(a2), "r"(a3), "r"(b0), "r"(b1));
            asm volatile(
                "mma.sync.aligned.m16n8k16.row.col.f32.f16.f16.f32 "
                "{%0,%1,%2,%3}, {%4,%5,%6,%7}, {%8,%9}, {%0,%1,%2,%3};"
                : "+f"(cf[2 * nt + 1][0]), "+f"(cf[2 * nt + 1][1]),
                  "+f"(cf[2 * nt + 1][2]), "+f"(cf[2 * nt + 1][3])
                : "r"(a0), "r"(a1), "r"(a2), "r"(a3), "r"(b2), "r"(b3));
        }
    }

    int g = lane >> 2, tg = lane & 3;
    int r1 = row0 + wr0 + g;
    int r2 = r1 + 8;
    bool ok1 = r1 < nrows, ok2 = r2 < nrows;
    float s1 = 1.f, s2 = 1.f;
    if (scale) {
        if (ok1) s1 = scale[r1];
        if (ok2) s2 = scale[r2];
    }
#pragma unroll
    for (int t = 0; t < 16; t++) {
        int col = t * 8 + 2 * tg;
        if (ok1) *(__half2*)&out[(size_t)r1 * 128 + col] =
            __floats2half2_rn(cf[t][0] * s1, cf[t][1] * s1);
        if (ok2) *(__half2*)&out[(size_t)r2 * 128 + col] =
            __floats2half2_rn(cf[t][2] * s2, cf[t][3] * s2);
    }
}

// ---------------------------------------------------------------------------
// Aggregate (CSR gather of fp16 rows): warp per node, lane owns 8B (uint2),
// 2-wide rounds with NEXT-pair index prefetch (breaks idx->row dependent
// chain: next idx loads overlap current row loads). fp32 accumulation.
// ---------------------------------------------------------------------------
__device__ __forceinline__ float4 h4f4(uint2 r) {
    __half2 a = *(__half2*)&r.x, b = *(__half2*)&r.y;
    float2 fa = __half22float2(a), fb = __half22float2(b);
    return make_float4(fa.x, fa.y, fb.x, fb.y);
}

__global__ void k_agg(const int* __restrict__ rowptr, const int* __restrict__ csr,
                      const __half* __restrict__ tmp, const float* __restrict__ dinv,
                      const float* __restrict__ edinv, const float* __restrict__ bias,
                      float* __restrict__ out, int n0, int ncnt) {
    int wi = (blockIdx.x * blockDim.x + threadIdx.x) >> 5;
    if (wi >= ncnt) return;
    int w = n0 + wi;
    int lane = threadIdx.x & 31;
    const uint2* t2 = (const uint2*)tmp;

    float4 self = h4f4(t2[(size_t)w * 32 + lane]);
    float se = edinv ? edinv[w] : 1.0f;
    float4 a = make_float4(self.x * se, self.y * se, self.z * se, self.w * se);
    float4 a2 = make_float4(0.f, 0.f, 0.f, 0.f);

    int e   = __ldg(rowptr + w);
    int end = __ldg(rowptr + w + 1);
    int cnt = end - e;

    if (edinv) {
        if (cnt >= 2) {
            int s0 = __ldg(csr + e), s1 = __ldg(csr + e + 1);
            e += 2;
            while (e + 1 < end) {
                int n0 = __ldg(csr + e), n1 = __ldg(csr + e + 1);
                float e0 = __ldg(edinv + s0), e1 = __ldg(edinv + s1);
                float4 v0 = h4f4(t2[(size_t)s0 * 32 + lane]);
                float4 v1 = h4f4(t2[(size_t)s1 * 32 + lane]);
                a.x = fmaf(v0.x, e0, a.x);  a.y = fmaf(v0.y, e0, a.y);
                a.z = fmaf(v0.z, e0, a.z);  a.w = fmaf(v0.w, e0, a.w);
                a2.x = fmaf(v1.x, e1, a2.x); a2.y = fmaf(v1.y, e1, a2.y);
                a2.z = fmaf(v1.z, e1, a2.z); a2.w = fmaf(v1.w, e1, a2.w);
                s0 = n0; s1 = n1;
                e += 2;
            }
            float e0 = __ldg(edinv + s0), e1 = __ldg(edinv + s1);
            float4 v0 = h4f4(t2[(size_t)s0 * 32 + lane]);
            float4 v1 = h4f4(t2[(size_t)s1 * 32 + lane]);
            a.x = fmaf(v0.x, e0, a.x);  a.y = fmaf(v0.y, e0, a.y);
            a.z = fmaf(v0.z, e0, a.z);  a.w = fmaf(v0.w, e0, a.w);
            a2.x = fmaf(v1.x, e1, a2.x); a2.y = fmaf(v1.y, e1, a2.y);
            a2.z = fmaf(v1.z, e1, a2.z); a2.w = fmaf(v1.w, e1, a2.w);
        }
        if (cnt & 1) {
            int s0 = __ldg(csr + end - 1);
            float e0 = __ldg(edinv + s0);
            float4 v0 = h4f4(t2[(size_t)s0 * 32 + lane]);
            a.x = fmaf(v0.x, e0, a.x); a.y = fmaf(v0.y, e0, a.y);
            a.z = fmaf(v0.z, e0, a.z); a.w = fmaf(v0.w, e0, a.w);
        }
    } else {
        if (cnt >= 2) {
            int s0 = __ldg(csr + e), s1 = __ldg(csr + e + 1);
            e += 2;
            while (e + 1 < end) {
                int n0 = __ldg(csr + e), n1 = __ldg(csr + e + 1);
                float4 v0 = h4f4(t2[(size_t)s0 * 32 + lane]);
                float4 v1 = h4f4(t2[(size_t)s1 * 32 + lane]);
                a.x += v0.x;  a.y += v0.y;  a.z += v0.z;  a.w += v0.w;
                a2.x += v1.x; a2.y += v1.y; a2.z += v1.z; a2.w += v1.w;
                s0 = n0; s1 = n1;
                e += 2;
            }
            float4 v0 = h4f4(t2[(size_t)s0 * 32 + lane]);
            float4 v1 = h4f4(t2[(size_t)s1 * 32 + lane]);
            a.x += v0.x;  a.y += v0.y;  a.z += v0.z;  a.w += v0.w;
            a2.x += v1.x; a2.y += v1.y; a2.z += v1.z; a2.w += v1.w;
        }
        if (cnt & 1) {
            int s0 = __ldg(csr + end - 1);
            float4 v0 = h4f4(t2[(size_t)s0 * 32 + lane]);
            a.x += v0.x; a.y += v0.y; a.z += v0.z; a.w += v0.w;
        }
    }
    a.x += a2.x; a.y += a2.y; a.z += a2.z; a.w += a2.w;

    float sc = dinv[w];
    float4 b = ((const float4*)bias)[lane];
    a.x = fmaxf(fmaf(a.x, sc, b.x), 0.0f);
    a.y = fmaxf(fmaf(a.y, sc, b.y), 0.0f);
    a.z = fmaxf(fmaf(a.z, sc, b.z), 0.0f);
    a.w = fmaxf(fmaf(a.w, sc, b.w), 0.0f);
    ((float4*)out)[(size_t)w * 32 + lane] = a;
}

// ---------------------------------------------------------------------------
// Classifier SIMT GEMM (BN=40), FFMA2 path (fp32-exact logits).
// ---------------------------------------------------------------------------
#define FFMA2(d, a, b) asm("fma.rn.f32x2 %0, %1, %2, %0;" : "+l"(d) : "l"(a), "l"(b))
union U64F2 { unsigned long long u; float2 f; };

template <int BN>
__global__ void k_gemm_cls(const float* __restrict__ A, const float* __restrict__ W,
                           const float* __restrict__ bias,
                           float* __restrict__ out0, int nrows) {
    constexpr int BM = 64;
    constexpr int TX = BN / 4;
    constexpr int TY = BM / 4;
    constexpr int NT = TX * TY;

    extern __shared__ float fsm[];
    float*  Ws = fsm;
    float2* Ad = (float2*)(fsm + 128 * BN);
    float*  As = (float*)(Ad + 128 * BM);

    const int tid  = threadIdx.x;
    const int row0 = blockIdx.x * BM;

    for (int idx = tid; idx < 128 * BN; idx += NT) Ws[idx] = W[idx];
    for (int idx = tid; idx < BM * 128; idx += NT) {
        int r = idx >> 7, k = idx & 127;
        int gr = row0 + r;
        As[r * 129 + k] = (gr < nrows) ? A[(size_t)gr * 128 + k] : 0.0f;
    }
    __syncthreads();
    for (int idx = tid; idx < 128 * BM; idx += NT) {
        int r = idx % BM, k = idx / BM;
        float v = As[r * 129 + k];
        Ad[idx] = make_float2(v, v);
    }
    __syncthreads();

    const int tc = tid % TX, tr = tid / TX;
    unsigned long long acc[4][2];
#pragma unroll
    for (int r = 0; r < 4; r++) { acc[r][0] = 0ull; acc[r][1] = 0ull; }

    const float2* adp = Ad + 4 * tr;
    const float*  wsp = Ws + 4 * tc;

#pragma unroll 8
    for (int k = 0; k < 128; k++) {
        ulonglong2 av0 = *(const ulonglong2*)(adp + (size_t)k * BM);
        ulonglong2 av1 = *(const ulonglong2*)(adp + (size_t)k * BM + 2);
        ulonglong2 wv  = *(const ulonglong2*)(wsp + (size_t)k * BN);
        FFMA2(acc[0][0], av0.x, wv.x); FFMA2(acc[0][1], av0.x, wv.y);
        FFMA2(acc[1][0], av0.y, wv.x); FFMA2(acc[1][1], av0.y, wv.y);
        FFMA2(acc[2][0], av1.x, wv.x); FFMA2(acc[2][1], av1.x, wv.y);
        FFMA2(acc[3][0], av1.y, wv.x); FFMA2(acc[3][1], av1.y, wv.y);
    }

#pragma unroll
    for (int r = 0; r < 4; r++) {
        int row = row0 + 4 * tr + r;
        if (row >= nrows) break;
        U64F2 u0, u1;
        u0.u = acc[r][0];
        u1.u = acc[r][1];
        float4 v = make_float4(u0.f.x + bias[4 * tc + 0], u0.f.y + bias[4 * tc + 1],
                               u1.f.x + bias[4 * tc + 2], u1.f.y + bias[4 * tc + 3]);
        *(float4*)(out0 + (size_t)row * BN + 4 * tc) = v;
    }
}

// ---------------------------------------------------------------------------
extern "C" void kernel_launch(void* const* d_in, const int* in_sizes, int n_in,
                              void* d_out, int out_size) {
    const float* x  = (const float*)d_in[0];
    const int*   ei = (const int*)d_in[1];
    const float* W1 = (const float*)d_in[2];
    const float* b1 = (const float*)d_in[3];
    const float* W2 = (const float*)d_in[4];
    const float* b2 = (const float*)d_in[5];
    const float* W3 = (const float*)d_in[6];
    const float* b3 = (const float*)d_in[7];
    const float* Wc = (const float*)d_in[8];
    const float* bc = (const float*)d_in[9];

    float* out_logits = (float*)d_out;                    // [NN,40]
    float* out_h      = (float*)d_out + (size_t)NN * 40;  // [NN,128]

    __half *tmpA, *tmpB;
    float *h, *dinv;
    int *deg, *rowptr, *cursor, *csr, *bsum;
    cudaGetSymbolAddress((void**)&tmpA,   g_tmpA);
    cudaGetSymbolAddress((void**)&tmpB,   g_tmpB);
    cudaGetSymbolAddress((void**)&h,      g_h);
    cudaGetSymbolAddress((void**)&dinv,   g_dinv);
    cudaGetSymbolAddress((void**)&deg,    g_deg);
    cudaGetSymbolAddress((void**)&rowptr, g_rowptr);
    cudaGetSymbolAddress((void**)&cursor, g_cursor);
    cudaGetSymbolAddress((void**)&csr,    g_csr);
    cudaGetSymbolAddress((void**)&bsum,   g_bsum);

    const int SM40 = 128 * 40 * 4 + 128 * 64 * 8 + 64 * 129 * 4;
    cudaFuncSetAttribute(k_gemm_mma, cudaFuncAttributeMaxDynamicSharedMemorySize, MMA_SMEM_BYTES);
    cudaFuncSetAttribute(k_gemm_cls<40>, cudaFuncAttributeMaxDynamicSharedMemorySize, SM40);

    cudaStream_t S = g_ctx.s;
    cudaEvent_t* E = g_ctx.e;

    // fork side stream off the capture (main) stream
    cudaEventRecord(E[0], 0);
    cudaStreamWaitEvent(S, E[0], 0);

    // ---- side stream: normalization + CSR build (5 launches, hidden) ----
    k_deg_init<<<(NN + 255) / 256, 256, 0, S>>>(deg);
    k_deg_count<<<(NE + 255) / 256, 256, 0, S>>>(ei, deg);
    k_scan1<<<NB, 512, 0, S>>>(deg, rowptr, bsum, dinv);
    k_scan3<<<NB, 512, 0, S>>>(rowptr, bsum, cursor);
    k_fill<<<(NE + 255) / 256, 256, 0, S>>>(ei, cursor, csr);
    cudaEventRecord(E[1], S);   // CSR + dinv ready

    // ---- main: layer 1 GEMM -> tmpA (unscaled; no dinv dependency) ----
    k_gemm_mma<<<(NN + 127) / 128, 256, MMA_SMEM_BYTES>>>(x, W1, nullptr, tmpA, NN);

    // agg layer 1 reads tmpA (dinv[src] per edge), writes h
    cudaStreamWaitEvent(0, E[1], 0);
    k_agg<<<HA / 8, 256>>>(rowptr, csr, tmpA, dinv, dinv, b1, h, 0, HA);
    cudaEventRecord(E[2], 0);   // h rows [0,HA) ready
    k_agg<<<HB / 8, 256>>>(rowptr, csr, tmpA, dinv, dinv, b1, h, HA, HB);

    // side: GEMM2-A (reads h[0:HA), writes tmpB) overlaps agg1-B (reads tmpA)
    cudaStreamWaitEvent(S, E[2], 0);
    k_gemm_mma<<<HA / 128, 256, MMA_SMEM_BYTES, S>>>(h, W2, dinv, tmpB, HA);
    cudaEventRecord(E[3], S);
    // main: GEMM2-B
    k_gemm_mma<<<(HB + 127) / 128, 256, MMA_SMEM_BYTES>>>(h + (size_t)HA * 128, W2,
                                                          dinv + HA, tmpB + (size_t)HA * 128, HB);
    cudaStreamWaitEvent(0, E[3], 0);
    // agg layer 2 reads tmpB, writes h
    k_agg<<<HA / 8, 256>>>(rowptr, csr, tmpB, dinv, nullptr, b2, h, 0, HA);
    cudaEventRecord(E[4], 0);
    k_agg<<<HB / 8, 256>>>(rowptr, csr, tmpB, dinv, nullptr, b2, h, HA, HB);

    // side: GEMM3-A (reads h[0:HA), writes tmpA) overlaps agg2-B (reads tmpB)
    cudaStreamWaitEvent(S, E[4], 0);
    k_gemm_mma<<<HA / 128, 256, MMA_SMEM_BYTES, S>>>(h, W3, dinv, tmpA, HA);
    cudaEventRecord(E[5], S);
    // main: GEMM3-B
    k_gemm_mma<<<(HB + 127) / 128, 256, MMA_SMEM_BYTES>>>(h + (size_t)HA * 128, W3,
                                                          dinv + HA, tmpA + (size_t)HA * 128, HB);
    cudaStreamWaitEvent(0, E[5], 0);
    // agg layer 3 reads tmpA, writes out_h
    k_agg<<<HA / 8, 256>>>(rowptr, csr, tmpA, dinv, nullptr, b3, out_h, 0, HA);
    cudaEventRecord(E[6], 0);
    k_agg<<<HB / 8, 256>>>(rowptr, csr, tmpA, dinv, nullptr, b3, out_h, HA, HB);

    // side: classifier-A (reads out_h[0:HA)) overlaps agg3-B (writes out_h[HA:))
    cudaStreamWaitEvent(S, E[6], 0);
    k_gemm_cls<40><<<HA / 64, 160, SM40, S>>>(out_h, Wc, bc, out_logits, HA);
    cudaEventRecord(E[7], S);
    // main: classifier-B
    k_gemm_cls<40><<<(HB + 63) / 64, 160, SM40>>>(out_h + (size_t)HA * 128, Wc, bc,
                                                  out_logits + (size_t)HA * 40, HB);
    // join side stream back into main before capture ends
    cudaStreamWaitEvent(0, E[7], 0);
}

// round 13
// speedup vs baseline: 1.0933x; 1.0933x over previous
#include <cuda_runtime.h>
#include <cuda_fp16.h>
#include <cstdint>

#define NN 50000
#define NE 800000
#define NB 98        // scan blocks: 98*512 >= 50000
#define HA 25088     // first-half nodes (multiple of 128, 64, 16)
#define HB (NN - HA) // 24912 (multiple of 8)

// ---------------------------------------------------------------------------
// Scratch (static device arrays: allocation-free per harness rules)
// ---------------------------------------------------------------------------
__device__ __half g_tmpA[NN * 128];
__device__ __half g_tmpB[NN * 128];
__device__ __half g_h16[NN * 128];   // fp16 hidden state (GEMM rounds to fp16 anyway)
__device__ float  g_dinv[NN];
__device__ int    g_deg[NN];
__device__ int    g_rowptr[NN + 1];
__device__ int    g_cursor[NN];
__device__ int    g_csr[NE];
__device__ int    g_bsum[NB];

// ---------------------------------------------------------------------------
// Host-side stream/event context (host resources only; created at static init)
// ---------------------------------------------------------------------------
struct Ctx {
    cudaStream_t s;
    cudaEvent_t e[12];
    Ctx() {
        cudaStreamCreateWithFlags(&s, cudaStreamNonBlocking);
        for (int i = 0; i < 12; i++) cudaEventCreateWithFlags(&e[i], cudaEventDisableTiming);
    }
};
static Ctx g_ctx;

// ---------------------------------------------------------------------------
// degree / normalization
// ---------------------------------------------------------------------------
__global__ void k_deg_init(int* __restrict__ deg) {
    int i = blockIdx.x * blockDim.x + threadIdx.x;
    if (i < NN) deg[i] = 1;  // self-loop
}
__global__ void k_deg_count(const int* __restrict__ ei, int* __restrict__ deg) {
    int e = blockIdx.x * blockDim.x + threadIdx.x;
    if (e < NE) atomicAdd(&deg[ei[NE + e]], 1);
}

// ---------------------------------------------------------------------------
// CSR build: scan1 (block-local exclusive scan + dinv), scan3 (+cross-block
// base reduction), cursor fill.
// ---------------------------------------------------------------------------
__global__ void k_scan1(const int* __restrict__ deg, int* __restrict__ rowptr,
                        int* __restrict__ bsum, float* __restrict__ dinv) {
    __shared__ int s[512];
    int tid = threadIdx.x;
    int i = blockIdx.x * 512 + tid;
    int d = (i < NN) ? deg[i] : 1;
    if (i < NN) dinv[i] = rsqrtf((float)d);
    int v = (i < NN) ? (d - 1) : 0;
    s[tid] = v;
    __syncthreads();
    for (int o = 1; o < 512; o <<= 1) {
        int t = (tid >= o) ? s[tid - o] : 0;
        __syncthreads();
        s[tid] += t;
        __syncthreads();
    }
    if (i < NN) rowptr[i] = s[tid] - v;
    if (tid == 511) bsum[blockIdx.x] = s[511];
}
__global__ void k_scan3(int* __restrict__ rowptr, const int* __restrict__ bsum,
                        int* __restrict__ cursor) {
    __shared__ int sb[128];
    int tid = threadIdx.x;
    if (tid < 128) sb[tid] = (tid < blockIdx.x && tid < NB) ? bsum[tid] : 0;
    __syncthreads();
    for (int o = 64; o > 0; o >>= 1) {
        if (tid < o) sb[tid] += sb[tid + o];
        __syncthreads();
    }
    int base = sb[0];
    int i = blockIdx.x * 512 + tid;
    if (i < NN) {
        int r = rowptr[i] + base;
        rowptr[i] = r;
        cursor[i] = r;
    }
    if (blockIdx.x == 0 && tid == 0) rowptr[NN] = NE;
}
__global__ void k_fill(const int* __restrict__ ei, int* __restrict__ cursor,
                       int* __restrict__ csr) {
    int e = blockIdx.x * blockDim.x + threadIdx.x;
    if (e >= NE) return;
    int dst = ei[NE + e];
    int pos = atomicAdd(&cursor[dst], 1);
    csr[pos] = ei[e];
}

// ---------------------------------------------------------------------------
// Tensor-core GEMM (HMMA mma.sync): 128x128 tile per block, 8 warps.
// out[row] = fp16( (A[row] @ W) [* scale[row]] ); fp32 accumulate.
// InT = float (layer 1, converts) or __half (layers 2/3, raw copy).
// ---------------------------------------------------------------------------
static constexpr int MMA_SMEM_BYTES = 2 * 128 * 136 * 2;   // 69632

template <typename InT>
__global__ void __launch_bounds__(256)
k_gemm_mma(const InT* __restrict__ A, const float* __restrict__ W,
           const float* __restrict__ scale, __half* __restrict__ out, int nrows) {
    extern __shared__ __half sh[];
    __half* As = sh;               // [128][136]
    __half* Bs = sh + 128 * 136;   // [128][136]  (W[k][n])
    const int tid = threadIdx.x;
    const int wid = tid >> 5, lane = tid & 31;
    const int row0 = blockIdx.x * 128;

    for (int i = tid; i < 4096; i += 256) {
        int k = i >> 5, nq = i & 31;
        float4 f = ((const float4*)W)[i];
        __half* p = Bs + k * 136 + nq * 4;
        *(__half2*)p       = __floats2half2_rn(f.x, f.y);
        *(__half2*)(p + 2) = __floats2half2_rn(f.z, f.w);
    }
    if constexpr (sizeof(InT) == 4) {
        // fp32 input: convert to fp16 on the way to smem
        for (int i = tid; i < 4096; i += 256) {
            int r = i >> 5, kq = i & 31;
            int grow = row0 + r;
            float4 f = make_float4(0.f, 0.f, 0.f, 0.f);
            if (grow < nrows) f = ((const float4*)A)[(size_t)grow * 32 + kq];
            __half* p = As + r * 136 + kq * 4;
            *(__half2*)p       = __floats2half2_rn(f.x, f.y);
            *(__half2*)(p + 2) = __floats2half2_rn(f.z, f.w);
        }
    } else {
        // fp16 input: straight 16B copy (8 halves per thread-iter)
        for (int i = tid; i < 2048; i += 256) {
            int r = i >> 4, kq8 = i & 15;
            int grow = row0 + r;
            uint4 v = make_uint4(0u, 0u, 0u, 0u);
            if (grow < nrows) v = ((const uint4*)A)[(size_t)grow * 16 + kq8];
            *(uint4*)(As + r * 136 + kq8 * 8) = v;
        }
    }
    __syncthreads();

    float cf[16][4];
#pragma unroll
    for (int t = 0; t < 16; t++) { cf[t][0] = cf[t][1] = cf[t][2] = cf[t][3] = 0.f; }

    const int wr0 = wid * 16;
    uint32_t a_base = (uint32_t)__cvta_generic_to_shared(
        As + (wr0 + (lane & 15)) * 136 + (lane >> 4) * 8);
    uint32_t b_base = (uint32_t)__cvta_generic_to_shared(
        Bs + (lane & 15) * 136 + (lane >> 4) * 8);

#pragma unroll
    for (int ks = 0; ks < 8; ks++) {
        uint32_t a0, a1, a2, a3;
        asm volatile("ldmatrix.sync.aligned.m8n8.x4.shared.b16 {%0,%1,%2,%3}, [%4];"
                     : "=r"(a0), "=r"(a1), "=r"(a2), "=r"(a3)
                     : "r"(a_base + ks * 16 * 2));
#pragma unroll
        for (int nt = 0; nt < 8; nt++) {
            uint32_t b0, b1, b2, b3;
            asm volatile("ldmatrix.sync.aligned.m8n8.x4.trans.shared.b16 {%0,%1,%2,%3}, [%4];"
                         : "=r"(b0), "=r"(b1), "=r"(b2), "=r"(b3)
                         : "r"(b_base + (ks * 16 * 136 + nt * 16) * 2));
            asm volatile(
                "mma.sync.aligned.m16n8k16.row.col.f32.f16.f16.f32 "
                "{%0,%1,%2,%3}, {%4,%5,%6,%7}, {%8,%9}, {%0,%1,%2,%3};"
                : "+f"(cf[2 * nt][0]), "+f"(cf[2 * nt][1]),
                  "+f"(cf[2 * nt][2]), "+f"(cf[2 * nt][3])
                : "r"(a0), "r"(a1), "r"(a2), "r"(a3), "r"(b0), "r"(b1));
            asm volatile(
                "mma.sync.aligned.m16n8k16.row.col.f32.f16.f16.f32 "
                "{%0,%1,%2,%3}, {%4,%5,%6,%7}, {%8,%9}, {%0,%1,%2,%3};"
                : "+f"(cf[2 * nt + 1][0]), "+f"(cf[2 * nt + 1][1]),
                  "+f"(cf[2 * nt + 1][2]), "+f"(cf[2 * nt + 1][3])
                : "r"(a0), "r"(a1), "r"(a2), "r"(a3), "r"(b2), "r"(b3));
        }
    }

    int g = lane >> 2, tg = lane & 3;
    int r1 = row0 + wr0 + g;
    int r2 = r1 + 8;
    bool ok1 = r1 < nrows, ok2 = r2 < nrows;
    float s1 = 1.f, s2 = 1.f;
    if (scale) {
        if (ok1) s1 = scale[r1];
        if (ok2) s2 = scale[r2];
    }
#pragma unroll
    for (int t = 0; t < 16; t++) {
        int col = t * 8 + 2 * tg;
        if (ok1) *(__half2*)&out[(size_t)r1 * 128 + col] =
            __floats2half2_rn(cf[t][0] * s1, cf[t][1] * s1);
        if (ok2) *(__half2*)&out[(size_t)r2 * 128 + col] =
            __floats2half2_rn(cf[t][2] * s2, cf[t][3] * s2);
    }
}

// ---------------------------------------------------------------------------
// Aggregate (CSR gather of fp16 rows): warp per node, lane owns 8B (uint2),
// 2-wide edge unroll, fp32 accumulation (R10 best-measured form, untouched).
// OutT = __half (layers 1/2 -> h16) or float (layer 3 -> out_h).
// ---------------------------------------------------------------------------
__device__ __forceinline__ float4 h4f4(uint2 r) {
    __half2 a = *(__half2*)&r.x, b = *(__half2*)&r.y;
    float2 fa = __half22float2(a), fb = __half22float2(b);
    return make_float4(fa.x, fa.y, fb.x, fb.y);
}

template <typename OutT>
__global__ void k_agg(const int* __restrict__ rowptr, const int* __restrict__ csr,
                      const __half* __restrict__ tmp, const float* __restrict__ dinv,
                      const float* __restrict__ edinv, const float* __restrict__ bias,
                      OutT* __restrict__ out, int n0, int ncnt) {
    int wi = (blockIdx.x * blockDim.x + threadIdx.x) >> 5;
    if (wi >= ncnt) return;
    int w = n0 + wi;
    int lane = threadIdx.x & 31;
    const uint2* t2 = (const uint2*)tmp;

    float4 self = h4f4(t2[(size_t)w * 32 + lane]);
    float se = edinv ? edinv[w] : 1.0f;
    float4 a = make_float4(self.x * se, self.y * se, self.z * se, self.w * se);
    float4 a2 = make_float4(0.f, 0.f, 0.f, 0.f);

    int e   = __ldg(rowptr + w);
    int end = __ldg(rowptr + w + 1);
    if (edinv) {
        for (; e + 1 < end; e += 2) {
            int s0 = __ldg(csr + e);
            int s1 = __ldg(csr + e + 1);
            float e0 = __ldg(edinv + s0), e1 = __ldg(edinv + s1);
            float4 v0 = h4f4(t2[(size_t)s0 * 32 + lane]);
            float4 v1 = h4f4(t2[(size_t)s1 * 32 + lane]);
            a.x = fmaf(v0.x, e0, a.x);  a.y = fmaf(v0.y, e0, a.y);
            a.z = fmaf(v0.z, e0, a.z);  a.w = fmaf(v0.w, e0, a.w);
            a2.x = fmaf(v1.x, e1, a2.x); a2.y = fmaf(v1.y, e1, a2.y);
            a2.z = fmaf(v1.z, e1, a2.z); a2.w = fmaf(v1.w, e1, a2.w);
        }
        if (e < end) {
            int s0 = __ldg(csr + e);
            float e0 = __ldg(edinv + s0);
            float4 v0 = h4f4(t2[(size_t)s0 * 32 + lane]);
            a.x = fmaf(v0.x, e0, a.x); a.y = fmaf(v0.y, e0, a.y);
            a.z = fmaf(v0.z, e0, a.z); a.w = fmaf(v0.w, e0, a.w);
        }
    } else {
        for (; e + 1 < end; e += 2) {
            int s0 = __ldg(csr + e);
            int s1 = __ldg(csr + e + 1);
            float4 v0 = h4f4(t2[(size_t)s0 * 32 + lane]);
            float4 v1 = h4f4(t2[(size_t)s1 * 32 + lane]);
            a.x += v0.x;  a.y += v0.y;  a.z += v0.z;  a.w += v0.w;
            a2.x += v1.x; a2.y += v1.y; a2.z += v1.z; a2.w += v1.w;
        }
        if (e < end) {
            int s0 = __ldg(csr + e);
            float4 v0 = h4f4(t2[(size_t)s0 * 32 + lane]);
            a.x += v0.x; a.y += v0.y; a.z += v0.z; a.w += v0.w;
        }
    }
    a.x += a2.x; a.y += a2.y; a.z += a2.z; a.w += a2.w;

    float sc = dinv[w];
    float4 b = ((const float4*)bias)[lane];
    a.x = fmaxf(fmaf(a.x, sc, b.x), 0.0f);
    a.y = fmaxf(fmaf(a.y, sc, b.y), 0.0f);
    a.z = fmaxf(fmaf(a.z, sc, b.z), 0.0f);
    a.w = fmaxf(fmaf(a.w, sc, b.w), 0.0f);

    if constexpr (sizeof(OutT) == 4) {
        ((float4*)out)[(size_t)w * 32 + lane] = a;
    } else {
        __half2 h0 = __floats2half2_rn(a.x, a.y);
        __half2 h1 = __floats2half2_rn(a.z, a.w);
        uint2 pk = make_uint2(*(uint32_t*)&h0, *(uint32_t*)&h1);
        ((uint2*)out)[(size_t)w * 32 + lane] = pk;
    }
}

// ---------------------------------------------------------------------------
// Classifier SIMT GEMM (BN=40), FFMA2 path (fp32-exact logits).
// ---------------------------------------------------------------------------
#define FFMA2(d, a, b) asm("fma.rn.f32x2 %0, %1, %2, %0;" : "+l"(d) : "l"(a), "l"(b))
union U64F2 { unsigned long long u; float2 f; };

template <int BN>
__global__ void k_gemm_cls(const float* __restrict__ A, const float* __restrict__ W,
                           const float* __restrict__ bias,
                           float* __restrict__ out0, int nrows) {
    constexpr int BM = 64;
    constexpr int TX = BN / 4;
    constexpr int TY = BM / 4;
    constexpr int NT = TX * TY;

    extern __shared__ float fsm[];
    float*  Ws = fsm;
    float2* Ad = (float2*)(fsm + 128 * BN);
    float*  As = (float*)(Ad + 128 * BM);

    const int tid  = threadIdx.x;
    const int row0 = blockIdx.x * BM;

    for (int idx = tid; idx < 128 * BN; idx += NT) Ws[idx] = W[idx];
    for (int idx = tid; idx < BM * 128; idx += NT) {
        int r = idx >> 7, k = idx & 127;
        int gr = row0 + r;
        As[r * 129 + k] = (gr < nrows) ? A[(size_t)gr * 128 + k] : 0.0f;
    }
    __syncthreads();
    for (int idx = tid; idx < 128 * BM; idx += NT) {
        int r = idx % BM, k = idx / BM;
        float v = As[r * 129 + k];
        Ad[idx] = make_float2(v, v);
    }
    __syncthreads();

    const int tc = tid % TX, tr = tid / TX;
    unsigned long long acc[4][2];
#pragma unroll
    for (int r = 0; r < 4; r++) { acc[r][0] = 0ull; acc[r][1] = 0ull; }

    const float2* adp = Ad + 4 * tr;
    const float*  wsp = Ws + 4 * tc;

#pragma unroll 8
    for (int k = 0; k < 128; k++) {
        ulonglong2 av0 = *(const ulonglong2*)(adp + (size_t)k * BM);
        ulonglong2 av1 = *(const ulonglong2*)(adp + (size_t)k * BM + 2);
        ulonglong2 wv  = *(const ulonglong2*)(wsp + (size_t)k * BN);
        FFMA2(acc[0][0], av0.x, wv.x); FFMA2(acc[0][1], av0.x, wv.y);
        FFMA2(acc[1][0], av0.y, wv.x); FFMA2(acc[1][1], av0.y, wv.y);
        FFMA2(acc[2][0], av1.x, wv.x); FFMA2(acc[2][1], av1.x, wv.y);
        FFMA2(acc[3][0], av1.y, wv.x); FFMA2(acc[3][1], av1.y, wv.y);
    }

#pragma unroll
    for (int r = 0; r < 4; r++) {
        int row = row0 + 4 * tr + r;
        if (row >= nrows) break;
        U64F2 u0, u1;
        u0.u = acc[r][0];
        u1.u = acc[r][1];
        float4 v = make_float4(u0.f.x + bias[4 * tc + 0], u0.f.y + bias[4 * tc + 1],
                               u1.f.x + bias[4 * tc + 2], u1.f.y + bias[4 * tc + 3]);
        *(float4*)(out0 + (size_t)row * BN + 4 * tc) = v;
    }
}

// ---------------------------------------------------------------------------
extern "C" void kernel_launch(void* const* d_in, const int* in_sizes, int n_in,
                              void* d_out, int out_size) {
    const float* x  = (const float*)d_in[0];
    const int*   ei = (const int*)d_in[1];
    const float* W1 = (const float*)d_in[2];
    const float* b1 = (const float*)d_in[3];
    const float* W2 = (const float*)d_in[4];
    const float* b2 = (const float*)d_in[5];
    const float* W3 = (const float*)d_in[6];
    const float* b3 = (const float*)d_in[7];
    const float* Wc = (const float*)d_in[8];
    const float* bc = (const float*)d_in[9];

    float* out_logits = (float*)d_out;                    // [NN,40]
    float* out_h      = (float*)d_out + (size_t)NN * 40;  // [NN,128]

    __half *tmpA, *tmpB, *h16;
    float *dinv;
    int *deg, *rowptr, *cursor, *csr, *bsum;
    cudaGetSymbolAddress((void**)&tmpA,   g_tmpA);
    cudaGetSymbolAddress((void**)&tmpB,   g_tmpB);
    cudaGetSymbolAddress((void**)&h16,    g_h16);
    cudaGetSymbolAddress((void**)&dinv,   g_dinv);
    cudaGetSymbolAddress((void**)&deg,    g_deg);
    cudaGetSymbolAddress((void**)&rowptr, g_rowptr);
    cudaGetSymbolAddress((void**)&cursor, g_cursor);
    cudaGetSymbolAddress((void**)&csr,    g_csr);
    cudaGetSymbolAddress((void**)&bsum,   g_bsum);

    const int SM40 = 128 * 40 * 4 + 128 * 64 * 8 + 64 * 129 * 4;
    cudaFuncSetAttribute(k_gemm_mma<float>, cudaFuncAttributeMaxDynamicSharedMemorySize, MMA_SMEM_BYTES);
    cudaFuncSetAttribute(k_gemm_mma<__half>, cudaFuncAttributeMaxDynamicSharedMemorySize, MMA_SMEM_BYTES);
    cudaFuncSetAttribute(k_gemm_cls<40>, cudaFuncAttributeMaxDynamicSharedMemorySize, SM40);

    cudaStream_t S = g_ctx.s;
    cudaEvent_t* E = g_ctx.e;

    // fork side stream off the capture (main) stream
    cudaEventRecord(E[0], 0);
    cudaStreamWaitEvent(S, E[0], 0);

    // ---- side stream: normalization + CSR build (5 launches, hidden) ----
    k_deg_init<<<(NN + 255) / 256, 256, 0, S>>>(deg);
    k_deg_count<<<(NE + 255) / 256, 256, 0, S>>>(ei, deg);
    k_scan1<<<NB, 512, 0, S>>>(deg, rowptr, bsum, dinv);
    k_scan3<<<NB, 512, 0, S>>>(rowptr, bsum, cursor);
    k_fill<<<(NE + 255) / 256, 256, 0, S>>>(ei, cursor, csr);
    cudaEventRecord(E[1], S);   // CSR + dinv ready

    // ---- main: layer 1 GEMM -> tmpA (unscaled; no dinv dependency) ----
    k_gemm_mma<float><<<(NN + 127) / 128, 256, MMA_SMEM_BYTES>>>(x, W1, nullptr, tmpA, NN);

    // agg layer 1 reads tmpA (dinv[src] per edge), writes h16
    cudaStreamWaitEvent(0, E[1], 0);
    k_agg<__half><<<HA / 8, 256>>>(rowptr, csr, tmpA, dinv, dinv, b1, h16, 0, HA);
    cudaEventRecord(E[2], 0);   // h16 rows [0,HA) ready
    k_agg<__half><<<HB / 8, 256>>>(rowptr, csr, tmpA, dinv, dinv, b1, h16, HA, HB);

    // side: GEMM2-A (reads h16[0:HA), writes tmpB) overlaps agg1-B (reads tmpA)
    cudaStreamWaitEvent(S, E[2], 0);
    k_gemm_mma<__half><<<HA / 128, 256, MMA_SMEM_BYTES, S>>>(h16, W2, dinv, tmpB, HA);
    cudaEventRecord(E[3], S);
    // main: GEMM2-B
    k_gemm_mma<__half><<<(HB + 127) / 128, 256, MMA_SMEM_BYTES>>>(h16 + (size_t)HA * 128, W2,
                                                                  dinv + HA, tmpB + (size_t)HA * 128, HB);
    cudaStreamWaitEvent(0, E[3], 0);
    // agg layer 2 reads tmpB, writes h16
    k_agg<__half><<<HA / 8, 256>>>(rowptr, csr, tmpB, dinv, nullptr, b2, h16, 0, HA);
    cudaEventRecord(E[4], 0);
    k_agg<__half><<<HB / 8, 256>>>(rowptr, csr, tmpB, dinv, nullptr, b2, h16, HA, HB);

    // side: GEMM3-A (reads h16[0:HA), writes tmpA) overlaps agg2-B (reads tmpB)
    cudaStreamWaitEvent(S, E[4], 0);
    k_gemm_mma<__half><<<HA / 128, 256, MMA_SMEM_BYTES, S>>>(h16, W3, dinv, tmpA, HA);
    cudaEventRecord(E[5], S);
    // main: GEMM3-B
    k_gemm_mma<__half><<<(HB + 127) / 128, 256, MMA_SMEM_BYTES>>>(h16 + (size_t)HA * 128, W3,
                                                                  dinv + HA, tmpA + (size_t)HA * 128, HB);
    cudaStreamWaitEvent(0, E[5], 0);
    // agg layer 3 reads tmpA, writes fp32 out_h
    k_agg<float><<<HA / 8, 256>>>(rowptr, csr, tmpA, dinv, nullptr, b3, out_h, 0, HA);
    cudaEventRecord(E[6], 0);
    k_agg<float><<<HB / 8, 256>>>(rowptr, csr, tmpA, dinv, nullptr, b3, out_h, HA, HB);

    // side: classifier-A (reads out_h[0:HA)) overlaps agg3-B (writes out_h[HA:))
    cudaStreamWaitEvent(S, E[6], 0);
    k_gemm_cls<40><<<HA / 64, 160, SM40, S>>>(out_h, Wc, bc, out_logits, HA);
    cudaEventRecord(E[7], S);
    // main: classifier-B
    k_gemm_cls<40><<<(HB + 63) / 64, 160, SM40>>>(out_h + (size_t)HA * 128, Wc, bc,
                                                  out_logits + (size_t)HA * 40, HB);
    // join side stream back into main before capture ends
    cudaStreamWaitEvent(0, E[7], 0);
}